// round 5
// baseline (speedup 1.0000x reference)
#include <cuda_runtime.h>
#include <math.h>

#define B1n 4
#define B2n 1024
#define Rn  64
#define Tn  8192
#define Ln  256

// Layout: 256 threads = 8 warps. Warp w handles receivers r = 8w .. 8w+7.
// Lane owns l = 8*lane .. 8*lane+7. Per (r,lane): three aligned LDG.128 fetch
// v[0..11]; a branch-free 2-stage select network extracts w[j]=v[d+j], j=0..8.

__global__ void __launch_bounds__(Ln, 3)
tof_predictor_kernel(const float* __restrict__ rec,        // (B1,R,T)
                     const float* __restrict__ samp,       // (B1,B2,3)
                     const float* __restrict__ emit,       // (3,)
                     const float* __restrict__ recv,       // (R,3)
                     float* __restrict__ out)              // (B1,B2)
{
    const int b2  = blockIdx.x;
    const int b1  = blockIdx.y;
    const int tid = threadIdx.x;

    __shared__ float2 s_pr[Rn];          // {frac, as_float(byteoff | d)}
    __shared__ float  s_s1[8 * Ln];      // per-warp partial sums of lerp
    __shared__ float  s_s2[8 * Ln];      // per-warp partial sums of lerp^2
    __shared__ float  s_red[16];

    // ---- precompute per-receiver base + frac (threads 0..63) ----
    const float fs_c = 96000.0f / 343.0f;
    if (tid < Rn) {
        const float* sp = samp + ((size_t)b1 * B2n + b2) * 3;
        float sx = sp[0], sy = sp[1], sz = sp[2];
        float ex = sx - emit[0], ey = sy - emit[1], ez = sz - emit[2];
        float d_e = sqrtf(ex * ex + ey * ey + ez * ez);
        const float* rp = recv + tid * 3;
        float rx = sx - rp[0], ry = sy - rp[1], rz = sz - rp[2];
        float d_r = sqrtf(rx * rx + ry * ry + rz * rz);
        float start = (d_e + d_r) * fs_c;
        int i0 = (int)floorf(start);
        i0 = min(max(i0, 0), Tn - 8 * 32 - 12);     // never fires for this geometry
        float frac = start - (float)i0;             // in [0,1)
        int i0a = i0 & ~3;
        int d   = i0 & 3;
        // byte offset of (r,i0a) within this b1's recordings; low 4 bits are 0,
        // so d rides in bits [0:2).
        int packed = ((tid * Tn + i0a) << 2) | d;
        s_pr[tid] = make_float2(frac, __int_as_float(packed));
    }
    __syncthreads();

    const int warp = tid >> 5;
    const int lane = tid & 31;

    // per-lane base: l-octet start, as byte pointer
    const char* recb = (const char*)(rec + (size_t)b1 * Rn * Tn + 8 * lane);

    float a[8], q[8];
#pragma unroll
    for (int j = 0; j < 8; ++j) { a[j] = 0.f; q[j] = 0.f; }

    const int r_lo = warp * 8;

#pragma unroll
    for (int c = 0; c < 4; ++c) {          // pairs of receivers
        float2 p0 = s_pr[r_lo + 2 * c];
        float2 p1 = s_pr[r_lo + 2 * c + 1];
        int o0 = __float_as_int(p0.y);
        int o1 = __float_as_int(p1.y);
        const float4* b0 = (const float4*)(recb + (o0 & ~3));
        const float4* b1p = (const float4*)(recb + (o1 & ~3));
        // issue all six loads back-to-back (no control flow in between)
        float4 A0 = __ldg(b0);
        float4 A1 = __ldg(b0 + 1);
        float4 B0 = __ldg(b0 + 2);
        float4 C0 = __ldg(b1p);
        float4 C1 = __ldg(b1p + 1);
        float4 D0 = __ldg(b1p + 2);

#pragma unroll
        for (int h = 0; h < 2; ++h) {
            float  f  = h ? p1.x : p0.x;
            int    d  = (h ? o1 : o0) & 3;
            float4 X0 = h ? C0 : A0;
            float4 X1 = h ? C1 : A1;
            float4 Y  = h ? D0 : B0;

            float v0 = X0.x, v1 = X0.y, v2 = X0.z, v3 = X0.w;
            float v4 = X1.x, v5 = X1.y, v6 = X1.z, v7 = X1.w;
            float v8 = Y.x,  v9 = Y.y,  v10 = Y.z, v11 = Y.w;

            const bool s2b = (d & 2) != 0;
            const bool s1b = (d & 1) != 0;

            // stage 1: shift by 2 (u[j] = v[j + 2*s2b]), need u0..u9
            float u0 = s2b ? v2  : v0;
            float u1 = s2b ? v3  : v1;
            float u2 = s2b ? v4  : v2;
            float u3 = s2b ? v5  : v3;
            float u4 = s2b ? v6  : v4;
            float u5 = s2b ? v7  : v5;
            float u6 = s2b ? v8  : v6;
            float u7 = s2b ? v9  : v7;
            float u8 = s2b ? v10 : v8;
            float u9 = s2b ? v11 : v9;

            // stage 2: shift by 1 (w[j] = u[j + s1b]), need w0..w8
            float w0 = s1b ? u1 : u0;
            float w1 = s1b ? u2 : u1;
            float w2 = s1b ? u3 : u2;
            float w3 = s1b ? u4 : u3;
            float w4 = s1b ? u5 : u4;
            float w5 = s1b ? u6 : u5;
            float w6 = s1b ? u7 : u6;
            float w7 = s1b ? u8 : u7;
            float w8 = s1b ? u9 : u8;

            float e0 = fmaf(f, w1 - w0, w0);
            float e1 = fmaf(f, w2 - w1, w1);
            float e2 = fmaf(f, w3 - w2, w2);
            float e3 = fmaf(f, w4 - w3, w3);
            float e4 = fmaf(f, w5 - w4, w4);
            float e5 = fmaf(f, w6 - w5, w5);
            float e6 = fmaf(f, w7 - w6, w6);
            float e7 = fmaf(f, w8 - w7, w7);

            a[0] += e0; q[0] = fmaf(e0, e0, q[0]);
            a[1] += e1; q[1] = fmaf(e1, e1, q[1]);
            a[2] += e2; q[2] = fmaf(e2, e2, q[2]);
            a[3] += e3; q[3] = fmaf(e3, e3, q[3]);
            a[4] += e4; q[4] = fmaf(e4, e4, q[4]);
            a[5] += e5; q[5] = fmaf(e5, e5, q[5]);
            a[6] += e6; q[6] = fmaf(e6, e6, q[6]);
            a[7] += e7; q[7] = fmaf(e7, e7, q[7]);
        }
    }

    // store per-warp partials (two float4 stores each)
    {
        float4* p1 = (float4*)&s_s1[warp * Ln + 8 * lane];
        float4* p2 = (float4*)&s_s2[warp * Ln + 8 * lane];
        p1[0] = make_float4(a[0], a[1], a[2], a[3]);
        p1[1] = make_float4(a[4], a[5], a[6], a[7]);
        p2[0] = make_float4(q[0], q[1], q[2], q[3]);
        p2[1] = make_float4(q[4], q[5], q[6], q[7]);
    }
    __syncthreads();

    // combine across the 8 warps: thread tid owns l = tid
    float S1 = 0.f, S2 = 0.f;
#pragma unroll
    for (int w = 0; w < 8; ++w) {
        S1 += s_s1[w * Ln + tid];
        S2 += s_s2[w * Ln + tid];
    }

    // Hann half-window at l = tid
    float wl = 0.5f - 0.5f * cosf(3.14159265358979323846f * (float)tid * (1.0f / 255.0f));
    float sw1 = wl * S1;               // sum_r xw
    float sw2 = (wl * wl) * S2;        // sum_r xw^2

    float num_p = sw2;
    float den_p = (sw2 - sw1 * sw1 * (1.0f / (float)Rn)) * (1.0f / (float)(Rn - 1));

    // ---- block reduction of (num_p, den_p) over 256 threads ----
    const unsigned FULL = 0xFFFFFFFFu;
#pragma unroll
    for (int off = 16; off > 0; off >>= 1) {
        num_p += __shfl_down_sync(FULL, num_p, off);
        den_p += __shfl_down_sync(FULL, den_p, off);
    }
    if (lane == 0) {
        s_red[warp * 2 + 0] = num_p;
        s_red[warp * 2 + 1] = den_p;
    }
    __syncthreads();
    if (warp == 0) {
        float n  = (lane < 8) ? s_red[lane * 2 + 0] : 0.0f;
        float dd = (lane < 8) ? s_red[lane * 2 + 1] : 0.0f;
#pragma unroll
        for (int off = 4; off > 0; off >>= 1) {
            n  += __shfl_down_sync(FULL, n, off);
            dd += __shfl_down_sync(FULL, dd, off);
        }
        if (lane == 0) {
            float num = n * (1.0f / ((float)Rn * (float)Ln));
            float den = dd * (1.0f / (float)Ln) + 0.001f;
            out[(size_t)b1 * B2n + b2] = num / den;
        }
    }
}

extern "C" void kernel_launch(void* const* d_in, const int* in_sizes, int n_in,
                              void* d_out, int out_size)
{
    const float* recordings         = (const float*)d_in[0];
    const float* sample_locations   = (const float*)d_in[1];
    const float* emitter_location   = (const float*)d_in[2];
    const float* receiver_locations = (const float*)d_in[3];
    float* out = (float*)d_out;

    dim3 grid(B2n, B1n);
    dim3 block(Ln);
    tof_predictor_kernel<<<grid, block>>>(recordings, sample_locations,
                                          emitter_location, receiver_locations, out);
}

// round 6
// speedup vs baseline: 1.1280x; 1.1280x over previous
#include <cuda_runtime.h>
#include <math.h>

#define B1n 4
#define B2n 1024
#define Rn  64
#define Tn  8192
#define Ln  256

// 256 threads = 64 l-threads x 4 r-groups (16 receivers each).
// Thread handles l = 4t..4t+3. Loads are 3x LDG.64 at 8B-aligned i0e+4t
// (i0e = i0 & ~1), fully lane-contiguous -> 12 L1 wavefronts per (block,r).
// The only misalignment left is d1 = i0 & 1, resolved by 5 FSELs (warp-uniform).

__global__ void __launch_bounds__(Ln)
tof_predictor_kernel(const float* __restrict__ rec,        // (B1,R,T)
                     const float* __restrict__ samp,       // (B1,B2,3)
                     const float* __restrict__ emit,       // (3,)
                     const float* __restrict__ recv,       // (R,3)
                     float* __restrict__ out)              // (B1,B2)
{
    const int b2  = blockIdx.x;
    const int b1  = blockIdx.y;
    const int tid = threadIdx.x;

    __shared__ float2 s_pr[Rn];          // {frac, as_float(((r*Tn+i0e)<<1)|d1)}
    __shared__ float  s_s1[4 * Ln];
    __shared__ float  s_s2[4 * Ln];
    __shared__ float  s_red[16];

    // ---- precompute per-receiver base + frac (threads 0..63) ----
    const float fs_c = 96000.0f / 343.0f;
    if (tid < Rn) {
        const float* sp = samp + ((size_t)b1 * B2n + b2) * 3;
        float sx = sp[0], sy = sp[1], sz = sp[2];
        float ex = sx - emit[0], ey = sy - emit[1], ez = sz - emit[2];
        float d_e = sqrtf(ex * ex + ey * ey + ez * ez);
        const float* rp = recv + tid * 3;
        float rx = sx - rp[0], ry = sy - rp[1], rz = sz - rp[2];
        float d_r = sqrtf(rx * rx + ry * ry + rz * rz);
        float start = (d_e + d_r) * fs_c;
        int i0 = (int)floorf(start);
        i0 = min(max(i0, 0), 7800);                 // never fires for this geometry
        float frac = start - (float)i0;             // in [0,1)
        int i0e = i0 & ~1;
        int d1  = i0 & 1;
        int packed = ((tid * Tn + i0e) << 1) | d1;
        s_pr[tid] = make_float2(frac, __int_as_float(packed));
    }
    __syncthreads();

    const int g = tid >> 6;        // r-group 0..3 -> r = g*16 .. g*16+15
    const int t = tid & 63;        // l-thread     -> l = 4t .. 4t+3

    // base as float2*, already offset by this thread's 4t elements (= 2t float2)
    const float2* recb2 = (const float2*)(rec + (size_t)b1 * Rn * Tn) + 2 * t;

    float a0 = 0.f, a1 = 0.f, a2 = 0.f, a3 = 0.f;
    float q0 = 0.f, q1 = 0.f, q2 = 0.f, q3 = 0.f;

    const int r_lo = g * 16;

#pragma unroll
    for (int c = 0; c < 8; ++c) {                  // 8 pairs of receivers
        float2 pA = s_pr[r_lo + 2 * c];
        float2 pB = s_pr[r_lo + 2 * c + 1];
        int oA = __float_as_int(pA.y);
        int oB = __float_as_int(pB.y);
        const float2* pa = recb2 + (oA >> 2);      // (r*Tn+i0e)/2
        const float2* pb = recb2 + (oB >> 2);

        // six 8B loads issued back-to-back (MLP=6, no control flow between)
        float2 A0 = __ldg(pa);
        float2 A1 = __ldg(pa + 1);
        float2 A2 = __ldg(pa + 2);
        float2 B0 = __ldg(pb);
        float2 B1 = __ldg(pb + 1);
        float2 B2 = __ldg(pb + 2);

#pragma unroll
        for (int h = 0; h < 2; ++h) {
            float f  = h ? pB.x : pA.x;
            bool  d1 = ((h ? oB : oA) & 1) != 0;
            float v0 = h ? B0.x : A0.x;
            float v1 = h ? B0.y : A0.y;
            float v2 = h ? B1.x : A1.x;
            float v3 = h ? B1.y : A1.y;
            float v4 = h ? B2.x : A2.x;
            float v5 = h ? B2.y : A2.y;

            // w_j = v[d1 + j], j = 0..4   (5 FSELs, warp-uniform predicate)
            float w0 = d1 ? v1 : v0;
            float w1 = d1 ? v2 : v1;
            float w2 = d1 ? v3 : v2;
            float w3 = d1 ? v4 : v3;
            float w4 = d1 ? v5 : v4;

            float e0 = fmaf(f, w1 - w0, w0);
            float e1 = fmaf(f, w2 - w1, w1);
            float e2 = fmaf(f, w3 - w2, w2);
            float e3 = fmaf(f, w4 - w3, w3);

            a0 += e0; q0 = fmaf(e0, e0, q0);
            a1 += e1; q1 = fmaf(e1, e1, q1);
            a2 += e2; q2 = fmaf(e2, e2, q2);
            a3 += e3; q3 = fmaf(e3, e3, q3);
        }
    }

    // store per-group partials
    {
        float4* p1 = (float4*)&s_s1[g * Ln + 4 * t];
        float4* p2 = (float4*)&s_s2[g * Ln + 4 * t];
        *p1 = make_float4(a0, a1, a2, a3);
        *p2 = make_float4(q0, q1, q2, q3);
    }
    __syncthreads();

    // combine across the 4 r-groups: thread tid owns l = tid
    float S1 = s_s1[tid] + s_s1[Ln + tid] + s_s1[2 * Ln + tid] + s_s1[3 * Ln + tid];
    float S2 = s_s2[tid] + s_s2[Ln + tid] + s_s2[2 * Ln + tid] + s_s2[3 * Ln + tid];

    // Hann half-window at l = tid
    float wl = 0.5f - 0.5f * cosf(3.14159265358979323846f * (float)tid * (1.0f / 255.0f));
    float sw1 = wl * S1;
    float sw2 = (wl * wl) * S2;

    float num_p = sw2;
    float den_p = (sw2 - sw1 * sw1 * (1.0f / (float)Rn)) * (1.0f / (float)(Rn - 1));

    const unsigned FULL = 0xFFFFFFFFu;
#pragma unroll
    for (int off = 16; off > 0; off >>= 1) {
        num_p += __shfl_down_sync(FULL, num_p, off);
        den_p += __shfl_down_sync(FULL, den_p, off);
    }
    const int warp = tid >> 5;
    const int lane = tid & 31;
    if (lane == 0) {
        s_red[warp * 2 + 0] = num_p;
        s_red[warp * 2 + 1] = den_p;
    }
    __syncthreads();
    if (warp == 0) {
        float n  = (lane < 8) ? s_red[lane * 2 + 0] : 0.0f;
        float dd = (lane < 8) ? s_red[lane * 2 + 1] : 0.0f;
#pragma unroll
        for (int off = 4; off > 0; off >>= 1) {
            n  += __shfl_down_sync(FULL, n, off);
            dd += __shfl_down_sync(FULL, dd, off);
        }
        if (lane == 0) {
            float num = n * (1.0f / ((float)Rn * (float)Ln));
            float den = dd * (1.0f / (float)Ln) + 0.001f;
            out[(size_t)b1 * B2n + b2] = num / den;
        }
    }
}

extern "C" void kernel_launch(void* const* d_in, const int* in_sizes, int n_in,
                              void* d_out, int out_size)
{
    const float* recordings         = (const float*)d_in[0];
    const float* sample_locations   = (const float*)d_in[1];
    const float* emitter_location   = (const float*)d_in[2];
    const float* receiver_locations = (const float*)d_in[3];
    float* out = (float*)d_out;

    dim3 grid(B2n, B1n);
    dim3 block(Ln);
    tof_predictor_kernel<<<grid, block>>>(recordings, sample_locations,
                                          emitter_location, receiver_locations, out);
}

// round 7
// speedup vs baseline: 1.2570x; 1.1144x over previous
#include <cuda_runtime.h>
#include <math.h>

#define B1n 4
#define B2n 1024
#define Rn  64
#define Tn  8192
#define Ln  256

// 256 threads = 64 l-threads x 4 r-groups (16 receivers each).
// Thread handles l = 4t..4t+3 via two aligned LDG.128 (lane-contiguous).
// Misalignment d = i0 & 3 resolved with a branch-free 11-FSEL network
// (warp-uniform predicates). Inner loop is software-pipelined (prefetch r+1).

__global__ void __launch_bounds__(Ln)
tof_predictor_kernel(const float* __restrict__ rec,        // (B1,R,T)
                     const float* __restrict__ samp,       // (B1,B2,3)
                     const float* __restrict__ emit,       // (3,)
                     const float* __restrict__ recv,       // (R,3)
                     float* __restrict__ out)              // (B1,B2)
{
    const int b2  = blockIdx.x;
    const int b1  = blockIdx.y;
    const int tid = threadIdx.x;

    __shared__ float2 s_pr[Rn];          // {frac, as_float(((r*Tn+i0a)<<2)|d)}
    __shared__ float  s_s1[4 * Ln];
    __shared__ float  s_s2[4 * Ln];
    __shared__ float  s_red[16];

    // ---- precompute per-receiver base + frac (threads 0..63) ----
    const float fs_c = 96000.0f / 343.0f;
    if (tid < Rn) {
        const float* sp = samp + ((size_t)b1 * B2n + b2) * 3;
        float sx = sp[0], sy = sp[1], sz = sp[2];
        float ex = sx - emit[0], ey = sy - emit[1], ez = sz - emit[2];
        float d_e = sqrtf(ex * ex + ey * ey + ez * ez);
        const float* rp = recv + tid * 3;
        float rx = sx - rp[0], ry = sy - rp[1], rz = sz - rp[2];
        float d_r = sqrtf(rx * rx + ry * ry + rz * rz);
        float start = (d_e + d_r) * fs_c;
        int i0 = (int)floorf(start);
        i0 = min(max(i0, 0), Tn - 2 - (Ln - 1) - 3);  // never fires in practice
        float frac = start - (float)i0;
        int i0a = i0 & ~3;
        int d   = i0 & 3;
        int packed = ((tid * Tn + i0a) << 2) | d;
        s_pr[tid] = make_float2(frac, __int_as_float(packed));
    }
    __syncthreads();

    const int g = tid >> 6;        // r-group 0..3 -> r = g*16 .. g*16+15
    const int t = tid & 63;        // l-thread     -> l = 4t .. 4t+3

    const float* recb = rec + (size_t)b1 * Rn * Tn + 4 * t;

    float a0 = 0.f, a1 = 0.f, a2 = 0.f, a3 = 0.f;
    float q0 = 0.f, q1 = 0.f, q2 = 0.f, q3 = 0.f;

    const int r_lo = g * 16;

    // ---- software-pipelined loop over 16 receivers ----
    float2 pr = s_pr[r_lo];
    {
        int o = __float_as_int(pr.y);
        const float4* p = (const float4*)(recb + (o >> 2));
        float4 A = __ldg(p);
        float4 B = __ldg(p + 1);

#pragma unroll
        for (int c = 0; c < 16; ++c) {
            // prefetch next receiver's params + data
            float2 prn;
            float4 An, Bn;
            if (c < 15) {
                prn = s_pr[r_lo + c + 1];
                int on = __float_as_int(prn.y);
                const float4* pn = (const float4*)(recb + (on >> 2));
                An = __ldg(pn);
                Bn = __ldg(pn + 1);
            }

            // compute on current
            float f = pr.x;
            int   d = __float_as_int(pr.y) & 3;
            bool s2b = (d & 2) != 0;
            bool s1b = (d & 1) != 0;

            float v0 = A.x, v1 = A.y, v2 = A.z, v3 = A.w;
            float v4 = B.x, v5 = B.y, v6 = B.z, v7 = B.w;

            // stage 1: shift by 2 -> u_j = v[j + 2*s2b], need u0..u5
            float u0 = s2b ? v2 : v0;
            float u1 = s2b ? v3 : v1;
            float u2 = s2b ? v4 : v2;
            float u3 = s2b ? v5 : v3;
            float u4 = s2b ? v6 : v4;
            float u5 = s2b ? v7 : v5;
            // stage 2: shift by 1 -> w_j = u[j + s1b], need w0..w4
            float w0 = s1b ? u1 : u0;
            float w1 = s1b ? u2 : u1;
            float w2 = s1b ? u3 : u2;
            float w3 = s1b ? u4 : u3;
            float w4 = s1b ? u5 : u4;

            float e0 = fmaf(f, w1 - w0, w0);
            float e1 = fmaf(f, w2 - w1, w1);
            float e2 = fmaf(f, w3 - w2, w2);
            float e3 = fmaf(f, w4 - w3, w3);

            a0 += e0; q0 = fmaf(e0, e0, q0);
            a1 += e1; q1 = fmaf(e1, e1, q1);
            a2 += e2; q2 = fmaf(e2, e2, q2);
            a3 += e3; q3 = fmaf(e3, e3, q3);

            // rotate pipeline
            pr = prn; A = An; B = Bn;
        }
    }

    // store per-group partials
    {
        float4* p1 = (float4*)&s_s1[g * Ln + 4 * t];
        float4* p2 = (float4*)&s_s2[g * Ln + 4 * t];
        *p1 = make_float4(a0, a1, a2, a3);
        *p2 = make_float4(q0, q1, q2, q3);
    }
    __syncthreads();

    // combine across the 4 r-groups: thread tid owns l = tid
    float S1 = s_s1[tid] + s_s1[Ln + tid] + s_s1[2 * Ln + tid] + s_s1[3 * Ln + tid];
    float S2 = s_s2[tid] + s_s2[Ln + tid] + s_s2[2 * Ln + tid] + s_s2[3 * Ln + tid];

    // Hann half-window at l = tid
    float wl = 0.5f - 0.5f * cosf(3.14159265358979323846f * (float)tid * (1.0f / 255.0f));
    float sw1 = wl * S1;
    float sw2 = (wl * wl) * S2;

    float num_p = sw2;
    float den_p = (sw2 - sw1 * sw1 * (1.0f / (float)Rn)) * (1.0f / (float)(Rn - 1));

    const unsigned FULL = 0xFFFFFFFFu;
#pragma unroll
    for (int off = 16; off > 0; off >>= 1) {
        num_p += __shfl_down_sync(FULL, num_p, off);
        den_p += __shfl_down_sync(FULL, den_p, off);
    }
    const int warp = tid >> 5;
    const int lane = tid & 31;
    if (lane == 0) {
        s_red[warp * 2 + 0] = num_p;
        s_red[warp * 2 + 1] = den_p;
    }
    __syncthreads();
    if (warp == 0) {
        float n  = (lane < 8) ? s_red[lane * 2 + 0] : 0.0f;
        float dd = (lane < 8) ? s_red[lane * 2 + 1] : 0.0f;
#pragma unroll
        for (int off = 4; off > 0; off >>= 1) {
            n  += __shfl_down_sync(FULL, n, off);
            dd += __shfl_down_sync(FULL, dd, off);
        }
        if (lane == 0) {
            float num = n * (1.0f / ((float)Rn * (float)Ln));
            float den = dd * (1.0f / (float)Ln) + 0.001f;
            out[(size_t)b1 * B2n + b2] = num / den;
        }
    }
}

extern "C" void kernel_launch(void* const* d_in, const int* in_sizes, int n_in,
                              void* d_out, int out_size)
{
    const float* recordings         = (const float*)d_in[0];
    const float* sample_locations   = (const float*)d_in[1];
    const float* emitter_location   = (const float*)d_in[2];
    const float* receiver_locations = (const float*)d_in[3];
    float* out = (float*)d_out;

    dim3 grid(B2n, B1n);
    dim3 block(Ln);
    tof_predictor_kernel<<<grid, block>>>(recordings, sample_locations,
                                          emitter_location, receiver_locations, out);
}